// round 16
// baseline (speedup 1.0000x reference)
#include <cuda_runtime.h>

// YoloLayer2: x (16, 3*85, 76, 76) f32 -> out (16, 3, 76, 76, 85) f32
// Persistent CTAs + cross-tile register prefetch on the R14 structure:
//  - 888 persistent blocks, ~5 tiles each; tile t+G's 6 float4 LDGs are
//    issued inside tile t's compute phase (consumed a full phase later ->
//    load latency exposed only once per block, not once per tile/wave)
//  - warp-shaped map (4 attrs x 8 quads/warp) -> conflict-free transposed STS
//  - .cs loads (input dead after read), default cached stores
//  - sigmoid via single-MUFU tanh.approx

#define NUM_B 16
#define NUM_A 3
#define DIM_H 76
#define DIM_W 76
#define HW (DIM_H * DIM_W)        // 5776
#define ATTR 85
#define TILE_P 64                 // pixels per tile (smem = 64*85*4 = 21760 B)
#define NTHREADS 256
#define NWARPS (NTHREADS / 32)
#define WITERS 44                 // 22 attr-groups (88 virtual) * 2 m-halves
#define MAXIT 6                   // ceil(WITERS / NWARPS)
#define TILES_PER_BA 91
#define TILES_TOTAL (NUM_B * NUM_A * TILES_PER_BA)   // 4368
#define NBLOCKS (148 * 6)         // 888 persistent blocks

// sigmoid(v) = 0.5*tanh(v/2) + 0.5  -- single MUFU (tanh.approx) + FMA
__device__ __forceinline__ float fsigmoid(float v) {
    float t;
    asm("tanh.approx.f32 %0, %1;" : "=f"(t) : "f"(v * 0.5f));
    return fmaf(t, 0.5f, 0.5f);
}

// streaming load: input is dead after one read
__device__ __forceinline__ float4 ldcs4(const float* p) {
    float4 r;
    asm("ld.global.cs.v4.f32 {%0,%1,%2,%3}, [%4];"
        : "=f"(r.x), "=f"(r.y), "=f"(r.z), "=f"(r.w) : "l"(p));
    return r;
}

__global__ __launch_bounds__(NTHREADS, 5)
void yolo_kernel(const float* __restrict__ x, float* __restrict__ out) {
    __shared__ float sm[TILE_P * ATTR];   // 21760 bytes

    const int tid  = threadIdx.x;
    const int warp = tid >> 5;
    const int lane = tid & 31;
    const int G    = gridDim.x;

    const int attr_lo = lane >> 3;        // 0..3 within attr-group
    const int m_lo    = lane & 7;         // 0..7 within m-half

    // static per-thread item geometry (tile-independent)
    int  attr_v[MAXIT], pl_v[MAXIT];
    bool aok[MAXIT];
    #pragma unroll
    for (int i = 0; i < MAXIT; i++) {
        const int wi = warp + i * NWARPS;
        attr_v[i] = ((wi >> 1) << 2) + attr_lo;   // 0..87 (88 virtual)
        pl_v[i]   = (((wi & 1) << 3) + m_lo) << 2;
        aok[i] = (wi < WITERS) && (attr_v[i] < ATTR);
    }

    float4 v[MAXIT];

    // ---- prefetch first tile (front-batched, MLP=6) ----
    int t = blockIdx.x;
    {
        const int ba     = t / TILES_PER_BA;
        const int ti     = t - ba * TILES_PER_BA;
        const int p0     = ti * TILE_P;
        const int nvalid = min(TILE_P, HW - p0);
        const float* bin = x + (size_t)ba * ATTR * HW + p0;
        #pragma unroll
        for (int i = 0; i < MAXIT; i++)
            if (aok[i] && pl_v[i] < nvalid)
                v[i] = ldcs4(bin + attr_v[i] * HW + pl_v[i]);
    }

    for (; t < TILES_TOTAL; t += G) {
        const int ba     = t / TILES_PER_BA;
        const int ti     = t - ba * TILES_PER_BA;
        const int a      = ba % NUM_A;
        const int p0     = ti * TILE_P;
        const int nvalid = min(TILE_P, HW - p0);   // 64, or 16 on last tile

        // anchor_w = masked[0:3]={10,13,16}; anchor_h = masked[1:4]={13,16,30}
        const float AW[3] = {10.0f, 13.0f, 16.0f};
        const float AH[3] = {13.0f, 16.0f, 30.0f};
        const float sw = AW[a] * (1.0f / 608.0f);
        const float sh = AH[a] * (1.0f / 608.0f);

        // next-tile pointers for cross-tile prefetch
        const int tn = t + G;
        const float* binn = nullptr;
        int nvalid_n = 0;
        if (tn < TILES_TOTAL) {
            const int ban = tn / TILES_PER_BA;
            const int tin = tn - ban * TILES_PER_BA;
            const int p0n = tin * TILE_P;
            nvalid_n = min(TILE_P, HW - p0n);
            binn = x + (size_t)ban * ATTR * HW + p0n;
        }

        // ---- phase 2: consume v[i] -> compute -> STS; reload v[i] with
        //      tile t+G's data immediately after consumption ----
        #pragma unroll
        for (int i = 0; i < MAXIT; i++) {
            const int attr = attr_v[i];
            const int pl   = pl_v[i];
            const bool cur_ok = aok[i] && (pl < nvalid);

            float vv[4];
            if (cur_ok) { vv[0] = v[i].x; vv[1] = v[i].y; vv[2] = v[i].z; vv[3] = v[i].w; }

            // cross-tile prefetch: issued early, consumed next tile
            if (binn && aok[i] && pl < nvalid_n)
                v[i] = ldcs4(binn + attr * HW + pl);

            if (cur_ok) {
                float r[4];
                if (attr >= 4) {
                    #pragma unroll
                    for (int k = 0; k < 4; k++) r[k] = fsigmoid(vv[k]);
                } else if (attr == 0) {
                    #pragma unroll
                    for (int k = 0; k < 4; k++) {
                        const int p   = p0 + pl + k;
                        const int wi2 = p % DIM_W;
                        r[k] = ((float)wi2 + fsigmoid(vv[k])) * (1.0f / 76.0f);
                    }
                } else if (attr == 1) {
                    #pragma unroll
                    for (int k = 0; k < 4; k++) {
                        const int p  = p0 + pl + k;
                        const int hj = p / DIM_W;
                        r[k] = ((float)hj + fsigmoid(vv[k])) * (1.0f / 76.0f);
                    }
                } else if (attr == 2) {
                    #pragma unroll
                    for (int k = 0; k < 4; k++) r[k] = __expf(vv[k]) * sw;
                } else { // attr == 3
                    #pragma unroll
                    for (int k = 0; k < 4; k++) r[k] = __expf(vv[k]) * sh;
                }
                // conflict-free transposed STS: (20m + attr) mod 32 all distinct
                float* row = sm + pl * ATTR + attr;
                #pragma unroll
                for (int k = 0; k < 4; k++) row[k * ATTR] = r[k];
            }
        }
        __syncthreads();

        // ---- store smem -> gmem (contiguous, float4, cached) ----
        {
            float* base_out = out + (size_t)(ba * HW + p0) * ATTR;
            const int total4 = (nvalid * ATTR) >> 2;
            const float4* s4 = (const float4*)sm;
            float4* o4 = (float4*)base_out;
            for (int k = tid; k < total4; k += NTHREADS)
                o4[k] = s4[k];
        }
        __syncthreads();   // smem reusable for next tile's STS
    }
}

extern "C" void kernel_launch(void* const* d_in, const int* in_sizes, int n_in,
                              void* d_out, int out_size) {
    const float* x = (const float*)d_in[0];
    float* out = (float*)d_out;
    yolo_kernel<<<NBLOCKS, NTHREADS>>>(x, out);
}

// round 17
// speedup vs baseline: 1.3869x; 1.3869x over previous
#include <cuda_runtime.h>

// YoloLayer2: x (16, 3*85, 76, 76) f32 -> out (16, 3, 76, 76, 85) f32
// R14 champion structure, two tiles per block with double-buffered smem:
// tile B's batched loads are issued before tile A's gmem store, hiding B's
// load latency behind A's store phase.

#define NUM_B 16
#define NUM_A 3
#define DIM_H 76
#define DIM_W 76
#define HW (DIM_H * DIM_W)        // 5776
#define ATTR 85
#define TILE_P 64                 // pixels per tile (buf = 64*85*4 = 21760 B)
#define NTHREADS 256
#define NWARPS (NTHREADS / 32)
#define WITERS 44                 // 22 attr-groups (88 virtual) * 2 m-halves
#define MAXIT 6                   // ceil(WITERS / NWARPS)
#define TILES_PER_BA 91           // tiles 0..90 per (b,a); last has 16 pixels

// sigmoid(v) = 0.5*tanh(v/2) + 0.5  -- single MUFU (tanh.approx) + FMA
__device__ __forceinline__ float fsigmoid(float v) {
    float t;
    asm("tanh.approx.f32 %0, %1;" : "=f"(t) : "f"(v * 0.5f));
    return fmaf(t, 0.5f, 0.5f);
}

// streaming load: input is dead after one read
__device__ __forceinline__ float4 ldcs4(const float* p) {
    float4 r;
    asm("ld.global.cs.v4.f32 {%0,%1,%2,%3}, [%4];"
        : "=f"(r.x), "=f"(r.y), "=f"(r.z), "=f"(r.w) : "l"(p));
    return r;
}

struct ItemGeom {
    int attr[MAXIT];
    int pl[MAXIT];
    bool aok[MAXIT];
};

// compute + conflict-free transposed STS for one tile's batch
__device__ __forceinline__ void compute_sts(
    const ItemGeom& g, const float4* v, float* __restrict__ buf,
    int p0, int nvalid, float sw, float sh)
{
    #pragma unroll
    for (int i = 0; i < MAXIT; i++) {
        const int attr = g.attr[i];
        const int pl   = g.pl[i];
        if (!(g.aok[i] && pl < nvalid)) continue;
        float vv[4] = {v[i].x, v[i].y, v[i].z, v[i].w};
        float r[4];

        if (attr >= 4) {
            #pragma unroll
            for (int k = 0; k < 4; k++) r[k] = fsigmoid(vv[k]);
        } else if (attr == 0) {
            #pragma unroll
            for (int k = 0; k < 4; k++) {
                const int p   = p0 + pl + k;
                const int wi2 = p % DIM_W;
                r[k] = ((float)wi2 + fsigmoid(vv[k])) * (1.0f / 76.0f);
            }
        } else if (attr == 1) {
            #pragma unroll
            for (int k = 0; k < 4; k++) {
                const int p  = p0 + pl + k;
                const int hj = p / DIM_W;
                r[k] = ((float)hj + fsigmoid(vv[k])) * (1.0f / 76.0f);
            }
        } else if (attr == 2) {
            #pragma unroll
            for (int k = 0; k < 4; k++) r[k] = __expf(vv[k]) * sw;
        } else { // attr == 3
            #pragma unroll
            for (int k = 0; k < 4; k++) r[k] = __expf(vv[k]) * sh;
        }

        // bank (20m + attr) mod 32: all 32 lanes distinct -> conflict-free
        float* row = buf + pl * ATTR + attr;
        #pragma unroll
        for (int k = 0; k < 4; k++) row[k * ATTR] = r[k];
    }
}

__global__ __launch_bounds__(NTHREADS)
void yolo_kernel(const float* __restrict__ x, float* __restrict__ out) {
    __shared__ float sm[2][TILE_P * ATTR];   // 2 * 21760 B = 43520 B

    const int tA = blockIdx.x * 2;           // first tile of the pair
    const int tB = tA + 1;
    const bool hasB = (tB < TILES_PER_BA);
    const int ba = blockIdx.y;               // b*3 + a, 0..47
    const int a  = ba % NUM_A;

    // anchor_w = masked[0:3]={10,13,16}; anchor_h = masked[1:4]={13,16,30}
    const float AW[3] = {10.0f, 13.0f, 16.0f};
    const float AH[3] = {13.0f, 16.0f, 30.0f};
    const float sw = AW[a] * (1.0f / 608.0f);
    const float sh = AH[a] * (1.0f / 608.0f);

    const int tid  = threadIdx.x;
    const int warp = tid >> 5;
    const int lane = tid & 31;
    const int attr_lo = lane >> 3;
    const int m_lo    = lane & 7;

    ItemGeom g;
    #pragma unroll
    for (int i = 0; i < MAXIT; i++) {
        const int wi = warp + i * NWARPS;
        g.attr[i] = ((wi >> 1) << 2) + attr_lo;   // 0..87 (88 virtual)
        g.pl[i]   = (((wi & 1) << 3) + m_lo) << 2;
        g.aok[i]  = (wi < WITERS) && (g.attr[i] < ATTR);
    }

    const int p0A     = tA * TILE_P;
    const int nvalidA = min(TILE_P, HW - p0A);
    const int p0B     = p0A + TILE_P;
    const int nvalidB = hasB ? min(TILE_P, HW - p0B) : 0;

    const float* __restrict__ base = x + (size_t)ba * ATTR * HW;
    const float* binA = base + p0A;
    const float* binB = base + p0B;

    float4 v[MAXIT];

    // ---- tile A: batched loads (MLP=6) ----
    #pragma unroll
    for (int i = 0; i < MAXIT; i++)
        if (g.aok[i] && g.pl[i] < nvalidA)
            v[i] = ldcs4(binA + g.attr[i] * HW + g.pl[i]);

    // ---- tile A: compute + STS ----
    compute_sts(g, v, sm[0], p0A, nvalidA, sw, sh);
    __syncthreads();

    // ---- tile B: batched loads issued BEFORE storing A ----
    if (hasB) {
        #pragma unroll
        for (int i = 0; i < MAXIT; i++)
            if (g.aok[i] && g.pl[i] < nvalidB)
                v[i] = ldcs4(binB + g.attr[i] * HW + g.pl[i]);
    }

    // ---- store tile A (B's loads in flight behind this) ----
    {
        float* base_out = out + (size_t)(ba * HW + p0A) * ATTR;
        const int total4 = (nvalidA * ATTR) >> 2;
        const float4* s4 = (const float4*)sm[0];
        float4* o4 = (float4*)base_out;
        for (int k = tid; k < total4; k += NTHREADS)
            o4[k] = s4[k];
    }

    if (hasB) {
        // ---- tile B: compute + STS (loads completed during A's store) ----
        compute_sts(g, v, sm[1], p0B, nvalidB, sw, sh);
        __syncthreads();

        // ---- store tile B ----
        float* base_out = out + (size_t)(ba * HW + p0B) * ATTR;
        const int total4 = (nvalidB * ATTR) >> 2;
        const float4* s4 = (const float4*)sm[1];
        float4* o4 = (float4*)base_out;
        for (int k = tid; k < total4; k += NTHREADS)
            o4[k] = s4[k];
    }
}

extern "C" void kernel_launch(void* const* d_in, const int* in_sizes, int n_in,
                              void* d_out, int out_size) {
    const float* x = (const float*)d_in[0];
    float* out = (float*)d_out;
    dim3 grid((TILES_PER_BA + 1) / 2, NUM_B * NUM_A);   // (46, 48)
    yolo_kernel<<<grid, NTHREADS>>>(x, out);
}